// round 1
// baseline (speedup 1.0000x reference)
#include <cuda_runtime.h>

#define HH 2048
#define WW 2048
#define MW 2047
#define NPIX (HH * WW)

// scratch ping-pong buffers for the iteration state (static: no runtime alloc)
__device__ float g_baseA[NPIX];
__device__ float g_baseB[NPIX];

// ---------------------------------------------------------------------------
// Stage 0: base0 = sigma*(dxT(d_x-b_x)+dyT(d_y-b_y)) + alpha*corr(STg, flip(w))
//          f     = gamma[0] * base0
// ---------------------------------------------------------------------------
__global__ __launch_bounds__(256) void stage0_kernel(
    const float* __restrict__ STg, const float* __restrict__ dX,
    const float* __restrict__ dY, const float* __restrict__ bX,
    const float* __restrict__ bY, const float* __restrict__ alpha_p,
    const float* __restrict__ sigma_p, const float* __restrict__ gamma,
    const float* __restrict__ w9, float* __restrict__ base,
    float* __restrict__ f)
{
    const int j = blockIdx.x * 32 + threadIdx.x;
    const int i = blockIdx.y * 8 + threadIdx.y;
    const float alpha = __ldg(alpha_p);
    const float sigma = __ldg(sigma_p);
    const int jm = (j - 1) & MW;
    const int im = (i - 1) & MW;
    const int ij = i * WW + j;

    float dxb_c = __ldg(&dX[ij]) - __ldg(&bX[ij]);
    float dxb_l = __ldg(&dX[i * WW + jm]) - __ldg(&bX[i * WW + jm]);
    float dyb_c = __ldg(&dY[ij]) - __ldg(&bY[ij]);
    float dyb_u = __ldg(&dY[im * WW + j]) - __ldg(&bY[im * WW + j]);
    float se = sigma * ((dxb_l - dxb_c) + (dyb_u - dyb_c));

    // alpha * circ_conv(STg, w[::-1,::-1]) : XLA conv = cross-correlation
    float conv = 0.f;
#pragma unroll
    for (int p = 0; p < 3; ++p) {
        const int r = (i + p - 1) & MW;
#pragma unroll
        for (int q = 0; q < 3; ++q) {
            const int c = (j + q - 1) & MW;
            conv = fmaf(__ldg(&STg[r * WW + c]),
                        __ldg(&w9[(2 - p) * 3 + (2 - q)]), conv);
        }
    }
    const float x = fmaf(alpha, conv, se);
    base[ij] = x;
    f[ij] = __ldg(&gamma[0]) * x;
}

// ---------------------------------------------------------------------------
// One iteration of _compute, fully fused:
//   o1 = corr(base, w); mask at even/even positions;
//   o2 = corr(mask, flip(w)); base_new = alpha*o2 + (beta0+sigma)*lap(base)
//   f += gamma[it] * base_new
// Block: 16x16 threads -> 32x32 output tile, each thread owns a parity-aligned
// 2x2 quad. Only the 17x17 even-lattice o1 corners are ever needed.
// ---------------------------------------------------------------------------
#define TS 32
#define BR 35   // base tile extent (32 outputs + halo 2 on the "low" side + 1)
__global__ __launch_bounds__(256) void iter_kernel(
    const float* __restrict__ bin, float* __restrict__ bout,
    float* __restrict__ f, const float* __restrict__ alpha_p,
    const float* __restrict__ beta0_p, const float* __restrict__ sigma_p,
    const float* __restrict__ gamma, const float* __restrict__ w9, int it)
{
    __shared__ float sb[BR][BR + 1];  // sb[r][c] = base[gy0-1+r, gx0-1+c]
    __shared__ float so[17][18];      // o1 at even corners of the tile

    const int tx = threadIdx.x, ty = threadIdx.y;
    const int gx0 = blockIdx.x * TS, gy0 = blockIdx.y * TS;

    float w[3][3];
#pragma unroll
    for (int p = 0; p < 3; ++p)
#pragma unroll
        for (int q = 0; q < 3; ++q) w[p][q] = __ldg(&w9[p * 3 + q]);

    const float alpha = __ldg(alpha_p);
    const float bs = __ldg(beta0_p) + __ldg(sigma_p);
    const float g = __ldg(&gamma[it]);

    // Load base tile with wrap
    for (int r = ty; r < BR; r += 16) {
        const int gr = ((gy0 - 1 + r) & MW) * WW;
        for (int c = tx; c < BR; c += 16) {
            const int gc = (gx0 - 1 + c) & MW;
            sb[r][c] = __ldg(&bin[gr + gc]);
        }
    }
    __syncthreads();

    // o1 at even corner (cy,cx): global (gy0+2cy, gx0+2cx) -> sb rows 2cy..2cy+2
    for (int cy = ty; cy < 17; cy += 16)
        for (int cx = tx; cx < 17; cx += 16) {
            float a = 0.f;
#pragma unroll
            for (int p = 0; p < 3; ++p)
#pragma unroll
                for (int q = 0; q < 3; ++q)
                    a = fmaf(sb[2 * cy + p][2 * cx + q], w[p][q], a);
            so[cy][cx] = a;
        }
    __syncthreads();

    const float o00 = so[ty][tx];
    const float o01 = so[ty][tx + 1];
    const float o10 = so[ty + 1][tx];
    const float o11 = so[ty + 1][tx + 1];

    // second conv (correlation with flipped w) restricted to even corners
    float r2[2][2];
    r2[0][0] = o00 * w[1][1];
    r2[0][1] = fmaf(o00, w[1][2], o01 * w[1][0]);
    r2[1][0] = fmaf(o00, w[2][1], o10 * w[0][1]);
    r2[1][1] = fmaf(o00, w[2][2],
               fmaf(o01, w[2][0],
               fmaf(o10, w[0][2], o11 * w[0][0])));

    const int ly = 2 * ty, lx = 2 * tx;
#pragma unroll
    for (int a = 0; a < 2; ++a)
#pragma unroll
        for (int b = 0; b < 2; ++b) {
            const int oy = ly + a, ox = lx + b;
            const float ctr = sb[oy + 1][ox + 1];
            const float lap = 4.f * ctr - sb[oy][ox + 1] - sb[oy + 2][ox + 1]
                              - sb[oy + 1][ox] - sb[oy + 1][ox + 2];
            const float res = fmaf(alpha, r2[a][b], bs * lap);
            const int gidx = (gy0 + oy) * WW + (gx0 + ox);
            bout[gidx] = res;
            f[gidx] = fmaf(g, res, f[gidx]);
        }
}

// ---------------------------------------------------------------------------
// Final shrinkage / Bregman update
// ---------------------------------------------------------------------------
__global__ __launch_bounds__(256) void final_kernel(
    const float* __restrict__ f, const float* __restrict__ bX,
    const float* __restrict__ bY, const float* __restrict__ beta1_p,
    const float* __restrict__ sigma_p,
    float* __restrict__ dxn, float* __restrict__ dyn,
    float* __restrict__ bxn, float* __restrict__ byn)
{
    const int j = blockIdx.x * 32 + threadIdx.x;
    const int i = blockIdx.y * 8 + threadIdx.y;
    const int ij = i * WW + j;

    const float fc = __ldg(&f[ij]);
    const float fr = __ldg(&f[i * WW + ((j + 1) & MW)]);
    const float fd = __ldg(&f[((i + 1) & MW) * WW + j]);
    const float dxf = fr - fc;
    const float dyf = fd - fc;
    const float bx = __ldg(&bX[ij]);
    const float by = __ldg(&bY[ij]);
    const float px = dxf + bx;
    const float py = dyf + by;
    const float norm = sqrtf(fmaf(px, px, py * py));
    const float thr = __ldg(beta1_p) / __ldg(sigma_p);
    const float shrink = fmaxf(norm - thr, 0.f) / (norm + 1e-8f);
    const float dx_new = px * shrink;
    const float dy_new = py * shrink;
    dxn[ij] = dx_new;
    dyn[ij] = dy_new;
    bxn[ij] = bx + dxf - dx_new;
    byn[ij] = by + dyf - dy_new;
}

extern "C" void kernel_launch(void* const* d_in, const int* in_sizes, int n_in,
                              void* d_out, int out_size)
{
    const float* STg   = (const float*)d_in[0];
    const float* dX    = (const float*)d_in[1];
    const float* dY    = (const float*)d_in[2];
    const float* bX    = (const float*)d_in[3];
    const float* bY    = (const float*)d_in[4];
    // d_in[5], d_in[6] = decim_row, decim_col (== 2, parity path specialized)
    const float* alpha = (const float*)d_in[7];
    const float* beta0 = (const float*)d_in[8];
    const float* beta1 = (const float*)d_in[9];
    const float* sigma = (const float*)d_in[10];
    const float* gamma = (const float*)d_in[11];
    const float* w9    = (const float*)d_in[12];

    float* out = (float*)d_out;
    float* f = out;  // f accumulates directly in output plane 0

    float *pA, *pB;
    cudaGetSymbolAddress((void**)&pA, g_baseA);
    cudaGetSymbolAddress((void**)&pB, g_baseB);

    dim3 b1(32, 8), g1(WW / 32, HH / 8);
    stage0_kernel<<<g1, b1>>>(STg, dX, dY, bX, bY, alpha, sigma, gamma, w9,
                              pA, f);

    dim3 b2(16, 16), g2(WW / TS, HH / TS);
    float* bi = pA;
    float* bo = pB;
    for (int it = 1; it <= 5; ++it) {
        iter_kernel<<<g2, b2>>>(bi, bo, f, alpha, beta0, sigma, gamma, w9, it);
        float* t = bi; bi = bo; bo = t;
    }

    final_kernel<<<g1, b1>>>(f, bX, bY, beta1, sigma,
                             out + NPIX, out + 2 * NPIX,
                             out + 3 * NPIX, out + 4 * NPIX);
}

// round 2
// speedup vs baseline: 1.2055x; 1.2055x over previous
#include <cuda_runtime.h>

#define HH 2048
#define WW 2048
#define MW 2047
#define NPIX (HH * WW)

#define CORE 64            // output tile
#define B0   85            // base0 patch: CORE+1 (f fwd diff) + 2*10 (5 iters x reach 2)
#define BP   86            // pitch
#define FAP  66            // f accum pitch (65 wide)
#define COP  42            // corner buffer pitch (max 41 wide)
#define NT   512

// base0 scratch (single plane; everything else lives in smem)
__device__ float g_base0[NPIX];

// ---------------------------------------------------------------------------
// Stage 0: base0 = sigma*(dxT(d_x-b_x)+dyT(d_y-b_y)) + alpha*corr(STg, flip(w))
// ---------------------------------------------------------------------------
__global__ __launch_bounds__(256) void stage0_kernel(
    const float* __restrict__ STg, const float* __restrict__ dX,
    const float* __restrict__ dY, const float* __restrict__ bX,
    const float* __restrict__ bY, const float* __restrict__ alpha_p,
    const float* __restrict__ sigma_p, const float* __restrict__ w9,
    float* __restrict__ base)
{
    const int j = blockIdx.x * 32 + threadIdx.x;
    const int i = blockIdx.y * 8 + threadIdx.y;
    const float alpha = __ldg(alpha_p);
    const float sigma = __ldg(sigma_p);
    const int jm = (j - 1) & MW;
    const int im = (i - 1) & MW;
    const int ij = i * WW + j;

    float dxb_c = __ldg(&dX[ij]) - __ldg(&bX[ij]);
    float dxb_l = __ldg(&dX[i * WW + jm]) - __ldg(&bX[i * WW + jm]);
    float dyb_c = __ldg(&dY[ij]) - __ldg(&bY[ij]);
    float dyb_u = __ldg(&dY[im * WW + j]) - __ldg(&bY[im * WW + j]);
    float se = sigma * ((dxb_l - dxb_c) + (dyb_u - dyb_c));

    float conv = 0.f;
#pragma unroll
    for (int p = 0; p < 3; ++p) {
        const int r = (i + p - 1) & MW;
#pragma unroll
        for (int q = 0; q < 3; ++q) {
            const int c = (j + q - 1) & MW;
            conv = fmaf(__ldg(&STg[r * WW + c]),
                        __ldg(&w9[(2 - p) * 3 + (2 - q)]), conv);
        }
    }
    base[ij] = fmaf(alpha, conv, se);
}

// ---------------------------------------------------------------------------
// One fused _compute iteration entirely in smem.
// in/out buffers share the coordinate frame: index (r,c) = global
// (gy0-10+r, gx0-10+c).  Region starts are even -> decimation lattice = even r,c.
// ---------------------------------------------------------------------------
template <int K>
__device__ __forceinline__ void iter_step(
    const float* __restrict__ in, float* __restrict__ out,
    float* __restrict__ FA, float* __restrict__ CO,
    float w0, float w1, float w2, float w3, float w4,
    float w5, float w6, float w7, float w8,
    float alpha, float bs, float g, int tid)
{
    constexpr int SIN  = B0 - 4 * (K - 1);   // input region size
    constexpr int ST   = 2 * (K - 1);        // input region start
    constexpr int C    = (SIN - 3) / 2;      // corners per dim
    constexpr int SOUT = SIN - 4;
    constexpr int OST  = ST + 2;

    // Phase A: first conv at even-lattice corners only (the decimation mask)
    for (int idx = tid; idx < C * C; idx += NT) {
        const int ci = idx / C;
        const int cj = idx - ci * C;
        const float* p = in + (ST + 1 + 2 * ci) * BP + (ST + 1 + 2 * cj);
        float a;
        a = fmaf(p[0], w0, p[1] * w1);
        a = fmaf(p[2], w2, a);
        a = fmaf(p[BP], w3, a);
        a = fmaf(p[BP + 1], w4, a);
        a = fmaf(p[BP + 2], w5, a);
        a = fmaf(p[2 * BP], w6, a);
        a = fmaf(p[2 * BP + 1], w7, a);
        a = fmaf(p[2 * BP + 2], w8, a);
        CO[ci * COP + cj] = a;
    }
    __syncthreads();

    // Phase B: second conv (flipped w) from corners + laplacian + f accum
    for (int idx = tid; idx < SOUT * SOUT; idx += NT) {
        const int qr = idx / SOUT;
        const int qc = idx - qr * SOUT;
        const int r = OST + qr;
        const int c = OST + qc;
        const float* p = in + r * BP + c;
        const float lap = 4.f * p[0] - p[-1] - p[1] - p[-BP] - p[BP];

        const int er = qr & 1, ec = qc & 1;
        const float* co0 = CO + (qr >> 1) * COP + (qc >> 1);
        const float o00 = co0[0];
        const float o01 = co0[ec];
        const float o10 = co0[er * COP];
        const float o11 = co0[er * COP + ec];

        // weight = w[1+(qr-2ci)][1+(qc-2cj)]  (branchless parity select)
        const float wr0c0 = er ? (ec ? w8 : w7) : (ec ? w5 : w4);
        const float wr0c1 = ec ? (er ? w6 : w3) : 0.f;
        const float wr1c0 = er ? (ec ? w2 : w1) : 0.f;
        const float wr1c1 = (er & ec) ? w0 : 0.f;

        float s2;
        s2 = fmaf(o00, wr0c0, o01 * wr0c1);
        s2 = fmaf(o10, wr1c0, s2);
        s2 = fmaf(o11, wr1c1, s2);

        const float res = fmaf(alpha, s2, bs * lap);
        if (K < 5) out[r * BP + c] = res;

        const int fr = r - 10, fc = c - 10;
        if (K == 5) {
            FA[fr * FAP + fc] = fmaf(g, res, FA[fr * FAP + fc]);
        } else {
            if ((unsigned)fr < 65u && (unsigned)fc < 65u)
                FA[fr * FAP + fc] = fmaf(g, res, FA[fr * FAP + fc]);
        }
    }
    __syncthreads();
}

// ---------------------------------------------------------------------------
// Mega kernel: load base0 patch, 5 fused iterations, f-accum, shrink epilogue
// ---------------------------------------------------------------------------
__global__ __launch_bounds__(NT, 2) void mega_kernel(
    const float* __restrict__ base0, const float* __restrict__ bX,
    const float* __restrict__ bY, const float* __restrict__ alpha_p,
    const float* __restrict__ beta0_p, const float* __restrict__ beta1_p,
    const float* __restrict__ sigma_p, const float* __restrict__ gamma,
    const float* __restrict__ w9, float* __restrict__ out)
{
    extern __shared__ float sm[];
    float* A  = sm;                    // 85*86
    float* B  = A + B0 * BP;           // 85*86
    float* FA = B + B0 * BP;           // 65*66
    float* CO = FA + 65 * FAP;         // 41*42

    const int tid = threadIdx.x;
    const int gx0 = blockIdx.x * CORE;
    const int gy0 = blockIdx.y * CORE;

    const float w0 = __ldg(&w9[0]), w1 = __ldg(&w9[1]), w2 = __ldg(&w9[2]);
    const float w3 = __ldg(&w9[3]), w4 = __ldg(&w9[4]), w5 = __ldg(&w9[5]);
    const float w6 = __ldg(&w9[6]), w7 = __ldg(&w9[7]), w8 = __ldg(&w9[8]);
    const float alpha = __ldg(alpha_p);
    const float bs = __ldg(beta0_p) + __ldg(sigma_p);

    // Load 85x85 base0 patch (periodic wrap)
    for (int idx = tid; idx < B0 * B0; idx += NT) {
        const int r = idx / B0;
        const int c = idx - r * B0;
        const int gi = (gy0 - 10 + r) & MW;
        const int gj = (gx0 - 10 + c) & MW;
        A[r * BP + c] = __ldg(&base0[gi * WW + gj]);
    }
    __syncthreads();

    // FA = gamma[0] * base0 over the f region [10,75)^2
    const float g0 = __ldg(&gamma[0]);
    for (int idx = tid; idx < 65 * 65; idx += NT) {
        const int r = idx / 65;
        const int c = idx - r * 65;
        FA[r * FAP + c] = g0 * A[(r + 10) * BP + (c + 10)];
    }
    // (ordering vs phase B of iter 1 is covered by iter_step's internal sync)

    iter_step<1>(A, B, FA, CO, w0,w1,w2,w3,w4,w5,w6,w7,w8, alpha, bs, __ldg(&gamma[1]), tid);
    iter_step<2>(B, A, FA, CO, w0,w1,w2,w3,w4,w5,w6,w7,w8, alpha, bs, __ldg(&gamma[2]), tid);
    iter_step<3>(A, B, FA, CO, w0,w1,w2,w3,w4,w5,w6,w7,w8, alpha, bs, __ldg(&gamma[3]), tid);
    iter_step<4>(B, A, FA, CO, w0,w1,w2,w3,w4,w5,w6,w7,w8, alpha, bs, __ldg(&gamma[4]), tid);
    iter_step<5>(A, B, FA, CO, w0,w1,w2,w3,w4,w5,w6,w7,w8, alpha, bs, __ldg(&gamma[5]), tid);

    // Final shrink / Bregman epilogue on the 64x64 core
    const float thr = __ldg(beta1_p) / __ldg(sigma_p);
    for (int idx = tid; idx < CORE * CORE; idx += NT) {
        const int r = idx >> 6;
        const int c = idx & 63;
        const float fc_ = FA[r * FAP + c];
        const float dxf = FA[r * FAP + c + 1] - fc_;
        const float dyf = FA[(r + 1) * FAP + c] - fc_;
        const int ij = (gy0 + r) * WW + (gx0 + c);
        const float bx = __ldg(&bX[ij]);
        const float by = __ldg(&bY[ij]);
        const float px = dxf + bx;
        const float py = dyf + by;
        const float norm = sqrtf(fmaf(px, px, py * py));
        const float shrink = fmaxf(norm - thr, 0.f) / (norm + 1e-8f);
        const float dxn = px * shrink;
        const float dyn = py * shrink;
        out[ij] = fc_;
        out[NPIX + ij] = dxn;
        out[2 * NPIX + ij] = dyn;
        out[3 * NPIX + ij] = bx + dxf - dxn;
        out[4 * NPIX + ij] = by + dyf - dyn;
    }
}

static const int SMEM_BYTES = (2 * B0 * BP + 65 * FAP + 41 * COP) * 4;

extern "C" void kernel_launch(void* const* d_in, const int* in_sizes, int n_in,
                              void* d_out, int out_size)
{
    const float* STg   = (const float*)d_in[0];
    const float* dX    = (const float*)d_in[1];
    const float* dY    = (const float*)d_in[2];
    const float* bX    = (const float*)d_in[3];
    const float* bY    = (const float*)d_in[4];
    const float* alpha = (const float*)d_in[7];
    const float* beta0 = (const float*)d_in[8];
    const float* beta1 = (const float*)d_in[9];
    const float* sigma = (const float*)d_in[10];
    const float* gamma = (const float*)d_in[11];
    const float* w9    = (const float*)d_in[12];

    float* out = (float*)d_out;

    float* pB0;
    cudaGetSymbolAddress((void**)&pB0, g_base0);

    dim3 b1(32, 8), g1(WW / 32, HH / 8);
    stage0_kernel<<<g1, b1>>>(STg, dX, dY, bX, bY, alpha, sigma, w9, pB0);

    cudaFuncSetAttribute(mega_kernel,
                         cudaFuncAttributeMaxDynamicSharedMemorySize,
                         SMEM_BYTES);
    dim3 g2(WW / CORE, HH / CORE);
    mega_kernel<<<g2, NT, SMEM_BYTES>>>(pB0, bX, bY, alpha, beta0, beta1,
                                        sigma, gamma, w9, out);
}

// round 3
// speedup vs baseline: 1.2609x; 1.0460x over previous
#include <cuda_runtime.h>

#define HH 2048
#define WW 2048
#define MW 2047
#define NPIX (HH * WW)

#define CORE 64
#define B0   85          // base0 patch extent
#define BP   87          // patch pitch (odd)
#define FAP  66          // f accumulator pitch (65x65 used)
#define COP  42          // corner buffer pitch (41x41 used + 1 pad row read)
#define NQ   41          // slot grid (corners / quads) per dim
#define NT   448
#define NSLOT 4

__device__ float g_base0[NPIX];

// ---------------------------------------------------------------------------
// Stage 0: base0 = sigma*(dxT(d_x-b_x)+dyT(d_y-b_y)) + alpha*corr(STg, flip(w))
// ---------------------------------------------------------------------------
__global__ __launch_bounds__(256) void stage0_kernel(
    const float* __restrict__ STg, const float* __restrict__ dX,
    const float* __restrict__ dY, const float* __restrict__ bX,
    const float* __restrict__ bY, const float* __restrict__ alpha_p,
    const float* __restrict__ sigma_p, const float* __restrict__ w9,
    float* __restrict__ base)
{
    const int j = blockIdx.x * 32 + threadIdx.x;
    const int i = blockIdx.y * 8 + threadIdx.y;
    const float alpha = __ldg(alpha_p);
    const float sigma = __ldg(sigma_p);
    const int ij = i * WW + j;

    const bool border = (blockIdx.x == 0) | (blockIdx.x == gridDim.x - 1) |
                        (blockIdx.y == 0) | (blockIdx.y == gridDim.y - 1);

    float se, conv;
    if (!border) {
        const int um = ij - WW, dp = ij + WW;
        float dxb_c = __ldg(&dX[ij]) - __ldg(&bX[ij]);
        float dxb_l = __ldg(&dX[ij - 1]) - __ldg(&bX[ij - 1]);
        float dyb_c = __ldg(&dY[ij]) - __ldg(&bY[ij]);
        float dyb_u = __ldg(&dY[um]) - __ldg(&bY[um]);
        se = sigma * ((dxb_l - dxb_c) + (dyb_u - dyb_c));
        // corr with flipped w: out += STg[i+p-1][j+q-1]*w[2-p][2-q]
        conv =               __ldg(&STg[um - 1]) * __ldg(&w9[8]);
        conv = fmaf(__ldg(&STg[um    ]), __ldg(&w9[7]), conv);
        conv = fmaf(__ldg(&STg[um + 1]), __ldg(&w9[6]), conv);
        conv = fmaf(__ldg(&STg[ij - 1]), __ldg(&w9[5]), conv);
        conv = fmaf(__ldg(&STg[ij    ]), __ldg(&w9[4]), conv);
        conv = fmaf(__ldg(&STg[ij + 1]), __ldg(&w9[3]), conv);
        conv = fmaf(__ldg(&STg[dp - 1]), __ldg(&w9[2]), conv);
        conv = fmaf(__ldg(&STg[dp    ]), __ldg(&w9[1]), conv);
        conv = fmaf(__ldg(&STg[dp + 1]), __ldg(&w9[0]), conv);
    } else {
        const int jm = (j - 1) & MW, im = (i - 1) & MW;
        float dxb_c = __ldg(&dX[ij]) - __ldg(&bX[ij]);
        float dxb_l = __ldg(&dX[i * WW + jm]) - __ldg(&bX[i * WW + jm]);
        float dyb_c = __ldg(&dY[ij]) - __ldg(&bY[ij]);
        float dyb_u = __ldg(&dY[im * WW + j]) - __ldg(&bY[im * WW + j]);
        se = sigma * ((dxb_l - dxb_c) + (dyb_u - dyb_c));
        conv = 0.f;
#pragma unroll
        for (int p = 0; p < 3; ++p) {
            const int r = (i + p - 1) & MW;
#pragma unroll
            for (int q = 0; q < 3; ++q) {
                const int c = (j + q - 1) & MW;
                conv = fmaf(__ldg(&STg[r * WW + c]),
                            __ldg(&w9[(2 - p) * 3 + (2 - q)]), conv);
            }
        }
    }
    base[ij] = fmaf(alpha, conv, se);
}

// ---------------------------------------------------------------------------
// One fused _compute iteration. Slot (a,b) on fixed 41x41 grid handles
// corner center (2a,2b) in phase A and output quad rows/cols (2a..2a+1) in
// phase B. Valid range for iteration K: a,b in [K, 42-K].
// ---------------------------------------------------------------------------
template <int K>
__device__ __forceinline__ void iter_step(
    const float* __restrict__ in, float* __restrict__ out,
    float* __restrict__ CO, float* __restrict__ FA,
    const int* sa, const int* sb, const int* sio,
    const int* sco, const int* sfa, const int* sfm,
    float w0, float w1, float w2, float w3, float w4,
    float w5, float w6, float w7, float w8,
    float alpha, float bs, float g)
{
    // Phase A: first conv at decimated (even-lattice) corners
#pragma unroll
    for (int s = 0; s < NSLOT; ++s) {
        const int a = sa[s], b = sb[s];
        if (a >= K && a <= 42 - K && b >= K && b <= 42 - K) {
            const float* p = in + sio[s];
            float acc = fmaf(p[0], w0, p[1] * w1);
            acc = fmaf(p[2], w2, acc);
            acc = fmaf(p[BP], w3, acc);
            acc = fmaf(p[BP + 1], w4, acc);
            acc = fmaf(p[BP + 2], w5, acc);
            acc = fmaf(p[2 * BP], w6, acc);
            acc = fmaf(p[2 * BP + 1], w7, acc);
            acc = fmaf(p[2 * BP + 2], w8, acc);
            CO[sco[s]] = acc;
        }
    }
    __syncthreads();

    // Phase B: second conv from corners + laplacian + f accumulation
#pragma unroll
    for (int s = 0; s < NSLOT; ++s) {
        const int a = sa[s], b = sb[s];
        if (a >= K && a <= 42 - K && b >= K && b <= 42 - K) {
            const float* p = in + sio[s];
            const float t00 = p[1],          t01 = p[2];
            const float l10 = p[BP],         l11 = p[BP + 1];
            const float l12 = p[BP + 2],     l13 = p[BP + 3];
            const float l20 = p[2 * BP],     l21 = p[2 * BP + 1];
            const float l22 = p[2 * BP + 2], l23 = p[2 * BP + 3];
            const float t30 = p[3 * BP + 1], t31 = p[3 * BP + 2];

            const float lap00 = 4.f * l11 - l10 - l12 - t00 - l21;
            const float lap01 = 4.f * l12 - l11 - l13 - t01 - l22;
            const float lap10 = 4.f * l21 - l20 - l22 - l11 - t30;
            const float lap11 = 4.f * l22 - l21 - l23 - l12 - t31;

            const float* co = CO + sco[s];
            const float o00 = co[0], o01 = co[1];
            const float o10 = co[COP], o11 = co[COP + 1];

            const float r00 = fmaf(alpha, o00 * w4, bs * lap00);
            const float r01 = fmaf(alpha, fmaf(o00, w5, o01 * w3), bs * lap01);
            const float r10 = fmaf(alpha, fmaf(o00, w7, o10 * w1), bs * lap10);
            const float r11 = fmaf(alpha,
                fmaf(o00, w8, fmaf(o01, w6, fmaf(o10, w2, o11 * w0))),
                bs * lap11);

            if (K < 5) {
                float* ob = out + sio[s] + BP + 1;   // pixel (2a,2b)
                const bool rh = (a <= 41 - K), ch = (b <= 41 - K);
                ob[0] = r00;
                if (ch) ob[1] = r01;
                if (rh) ob[BP] = r10;
                if (rh && ch) ob[BP + 1] = r11;
            }

            const int fm = sfm[s];
            float* fp = FA + sfa[s];
            if ((fm & 5) == 5)   fp[0]       = fmaf(g, r00, fp[0]);
            if ((fm & 9) == 9)   fp[1]       = fmaf(g, r01, fp[1]);
            if ((fm & 6) == 6)   fp[FAP]     = fmaf(g, r10, fp[FAP]);
            if ((fm & 10) == 10) fp[FAP + 1] = fmaf(g, r11, fp[FAP + 1]);
        }
    }
    __syncthreads();
}

// ---------------------------------------------------------------------------
// Mega kernel
// ---------------------------------------------------------------------------
__global__ __launch_bounds__(NT, 2) void mega_kernel(
    const float* __restrict__ base0, const float* __restrict__ bX,
    const float* __restrict__ bY, const float* __restrict__ alpha_p,
    const float* __restrict__ beta0_p, const float* __restrict__ beta1_p,
    const float* __restrict__ sigma_p, const float* __restrict__ gamma,
    const float* __restrict__ w9, float* __restrict__ out)
{
    extern __shared__ float sm[];
    float* A  = sm;                       // 85*87
    float* B  = A + B0 * BP;              // 85*87
    float* FA = B + B0 * BP;              // 65*66
    float* CO = FA + 65 * FAP;            // 42*42

    const int tid = threadIdx.x;
    const int gx0 = blockIdx.x * CORE;
    const int gy0 = blockIdx.y * CORE;

    const float w0 = __ldg(&w9[0]), w1 = __ldg(&w9[1]), w2 = __ldg(&w9[2]);
    const float w3 = __ldg(&w9[3]), w4 = __ldg(&w9[4]), w5 = __ldg(&w9[5]);
    const float w6 = __ldg(&w9[6]), w7 = __ldg(&w9[7]), w8 = __ldg(&w9[8]);
    const float alpha = __ldg(alpha_p);
    const float bs = __ldg(beta0_p) + __ldg(sigma_p);

    // --- fixed slot precompute --------------------------------------------
    int sa[NSLOT], sb[NSLOT], sio[NSLOT], sco[NSLOT], sfa[NSLOT], sfm[NSLOT];
#pragma unroll
    for (int s = 0; s < NSLOT; ++s) {
        const int q = tid + s * NT;
        const int a = q / NQ + 1;
        const int b = q - (a - 1) * NQ + 1;
        sa[s] = a; sb[s] = b;
        sio[s] = (2 * a - 1) * BP + (2 * b - 1);  // top-left of 3x3 at (2a,2b)
        sco[s] = (a - 1) * COP + (b - 1);
        sfa[s] = (2 * a - 10) * FAP + (2 * b - 10);
        sfm[s] = ((a >= 5 && a <= 37) ? 1 : 0) | ((a >= 5 && a <= 36) ? 2 : 0) |
                 ((b >= 5 && b <= 37) ? 4 : 0) | ((b >= 5 && b <= 36) ? 8 : 0);
    }

    // --- load 85x85 base0 patch (periodic wrap) ---------------------------
    for (int idx = tid; idx < B0 * B0; idx += NT) {
        const int r = idx / B0;
        const int c = idx - r * B0;
        A[r * BP + c] = __ldg(&base0[((gy0 - 10 + r) & MW) * WW +
                                     ((gx0 - 10 + c) & MW)]);
    }
    __syncthreads();

    // --- FA = gamma[0] * base0 over f region [10,75)^2 --------------------
    const float g0 = __ldg(&gamma[0]);
    for (int idx = tid; idx < 65 * 65; idx += NT) {
        const int r = idx / 65;
        const int c = idx - r * 65;
        FA[r * FAP + c] = g0 * A[(r + 10) * BP + (c + 10)];
    }
    __syncthreads();

    iter_step<1>(A, B, CO, FA, sa, sb, sio, sco, sfa, sfm,
                 w0, w1, w2, w3, w4, w5, w6, w7, w8, alpha, bs, __ldg(&gamma[1]));
    iter_step<2>(B, A, CO, FA, sa, sb, sio, sco, sfa, sfm,
                 w0, w1, w2, w3, w4, w5, w6, w7, w8, alpha, bs, __ldg(&gamma[2]));
    iter_step<3>(A, B, CO, FA, sa, sb, sio, sco, sfa, sfm,
                 w0, w1, w2, w3, w4, w5, w6, w7, w8, alpha, bs, __ldg(&gamma[3]));
    iter_step<4>(B, A, CO, FA, sa, sb, sio, sco, sfa, sfm,
                 w0, w1, w2, w3, w4, w5, w6, w7, w8, alpha, bs, __ldg(&gamma[4]));
    iter_step<5>(A, B, CO, FA, sa, sb, sio, sco, sfa, sfm,
                 w0, w1, w2, w3, w4, w5, w6, w7, w8, alpha, bs, __ldg(&gamma[5]));

    // --- shrink / Bregman epilogue on 64x64 core --------------------------
    const float thr = __ldg(beta1_p) / __ldg(sigma_p);
    for (int idx = tid; idx < CORE * CORE; idx += NT) {
        const int r = idx >> 6;
        const int c = idx & 63;
        const float fc_ = FA[r * FAP + c];
        const float dxf = FA[r * FAP + c + 1] - fc_;
        const float dyf = FA[(r + 1) * FAP + c] - fc_;
        const int ij = (gy0 + r) * WW + (gx0 + c);
        const float bx = __ldg(&bX[ij]);
        const float by = __ldg(&bY[ij]);
        const float px = dxf + bx;
        const float py = dyf + by;
        const float norm = sqrtf(fmaf(px, px, py * py));
        const float shrink = fmaxf(norm - thr, 0.f) / (norm + 1e-8f);
        const float dxn = px * shrink;
        const float dyn = py * shrink;
        out[ij] = fc_;
        out[NPIX + ij] = dxn;
        out[2 * NPIX + ij] = dyn;
        out[3 * NPIX + ij] = bx + dxf - dxn;
        out[4 * NPIX + ij] = by + dyf - dyn;
    }
}

static const int SMEM_BYTES = (2 * B0 * BP + 65 * FAP + COP * COP) * 4;

extern "C" void kernel_launch(void* const* d_in, const int* in_sizes, int n_in,
                              void* d_out, int out_size)
{
    const float* STg   = (const float*)d_in[0];
    const float* dX    = (const float*)d_in[1];
    const float* dY    = (const float*)d_in[2];
    const float* bX    = (const float*)d_in[3];
    const float* bY    = (const float*)d_in[4];
    const float* alpha = (const float*)d_in[7];
    const float* beta0 = (const float*)d_in[8];
    const float* beta1 = (const float*)d_in[9];
    const float* sigma = (const float*)d_in[10];
    const float* gamma = (const float*)d_in[11];
    const float* w9    = (const float*)d_in[12];

    float* out = (float*)d_out;

    float* pB0;
    cudaGetSymbolAddress((void**)&pB0, g_base0);

    dim3 b1(32, 8), g1(WW / 32, HH / 8);
    stage0_kernel<<<g1, b1>>>(STg, dX, dY, bX, bY, alpha, sigma, w9, pB0);

    cudaFuncSetAttribute(mega_kernel,
                         cudaFuncAttributeMaxDynamicSharedMemorySize,
                         SMEM_BYTES);
    dim3 g2(WW / CORE, HH / CORE);
    mega_kernel<<<g2, NT, SMEM_BYTES>>>(pB0, bX, bY, alpha, beta0, beta1,
                                        sigma, gamma, w9, out);
}

// round 5
// speedup vs baseline: 1.5814x; 1.2542x over previous
#include <cuda_runtime.h>

#define HH 2048
#define WW 2048
#define MW 2047
#define NPIX (HH * WW)

#define CORE 64
#define B0   85
#define BP   88            // even pitch -> quad columns 8B-aligned
#define FAP  66
#define COP  42
#define NQ   41
#define NT   448
#define NSLOT 4
#define CO_DUMP (COP * COP)        // idle-slot dump cell
#define CO_SIZE (COP * COP + 48)   // covers dump reads
#define ASIZE (B0 * BP)
#define SIO_IDLE (BP + 1)          // slot (a=1,b=1): odd offset like real slots

__device__ float g_base0[NPIX];

__device__ __forceinline__ float2 lds2(const float* p) {
    return *reinterpret_cast<const float2*>(p);
}
__device__ __forceinline__ void sts2(float* p, float x, float y) {
    *reinterpret_cast<float2*>(p) = make_float2(x, y);
}

// ---------------------------------------------------------------------------
// Stage 0: base0 = sigma*(dxT(d_x-b_x)+dyT(d_y-b_y)) + alpha*corr(STg, flip(w))
// 2 pixels per thread, vectorized interior path.
// ---------------------------------------------------------------------------
__global__ __launch_bounds__(256) void stage0_kernel(
    const float* __restrict__ STg, const float* __restrict__ dX,
    const float* __restrict__ dY, const float* __restrict__ bX,
    const float* __restrict__ bY, const float* __restrict__ alpha_p,
    const float* __restrict__ sigma_p, const float* __restrict__ w9,
    float* __restrict__ base)
{
    const int jp = blockIdx.x * 32 + threadIdx.x;
    const int j = 2 * jp;
    const int i = blockIdx.y * 8 + threadIdx.y;
    const float alpha = __ldg(alpha_p);
    const float sigma = __ldg(sigma_p);
    const int ij = i * WW + j;

    const bool border = (blockIdx.x == 0) | (blockIdx.x == gridDim.x - 1) |
                        (blockIdx.y == 0) | (blockIdx.y == gridDim.y - 1);

    if (!border) {
        const int um = ij - WW, dp = ij + WW;
        const float2 sC = __ldg((const float2*)(STg + ij));
        const float  sL = __ldg(&STg[ij - 1]),  sR = __ldg(&STg[ij + 2]);
        const float2 sU = __ldg((const float2*)(STg + um));
        const float  sUL = __ldg(&STg[um - 1]), sUR = __ldg(&STg[um + 2]);
        const float2 sD = __ldg((const float2*)(STg + dp));
        const float  sDL = __ldg(&STg[dp - 1]), sDR = __ldg(&STg[dp + 2]);

        const float w0 = __ldg(&w9[0]), w1 = __ldg(&w9[1]), w2 = __ldg(&w9[2]);
        const float w3 = __ldg(&w9[3]), w4 = __ldg(&w9[4]), w5 = __ldg(&w9[5]);
        const float w6 = __ldg(&w9[6]), w7 = __ldg(&w9[7]), w8 = __ldg(&w9[8]);

        float c0 = sUL * w8;
        c0 = fmaf(sU.x, w7, c0); c0 = fmaf(sU.y, w6, c0);
        c0 = fmaf(sL, w5, c0);   c0 = fmaf(sC.x, w4, c0);
        c0 = fmaf(sC.y, w3, c0); c0 = fmaf(sDL, w2, c0);
        c0 = fmaf(sD.x, w1, c0); c0 = fmaf(sD.y, w0, c0);

        float c1 = sU.x * w8;
        c1 = fmaf(sU.y, w7, c1); c1 = fmaf(sUR, w6, c1);
        c1 = fmaf(sC.x, w5, c1); c1 = fmaf(sC.y, w4, c1);
        c1 = fmaf(sR, w3, c1);   c1 = fmaf(sD.x, w2, c1);
        c1 = fmaf(sD.y, w1, c1); c1 = fmaf(sDR, w0, c1);

        const float2 dxC = __ldg((const float2*)(dX + ij));
        const float  dxL = __ldg(&dX[ij - 1]);
        const float2 bxC = __ldg((const float2*)(bX + ij));
        const float  bxL = __ldg(&bX[ij - 1]);
        const float2 dyC = __ldg((const float2*)(dY + ij));
        const float2 dyU = __ldg((const float2*)(dY + um));
        const float2 byC = __ldg((const float2*)(bY + ij));
        const float2 byU = __ldg((const float2*)(bY + um));

        const float dxb0 = dxC.x - bxC.x, dxb1 = dxC.y - bxC.y;
        const float dxbl0 = dxL - bxL;
        const float se0 = sigma * ((dxbl0 - dxb0) + ((dyU.x - byU.x) - (dyC.x - byC.x)));
        const float se1 = sigma * ((dxb0 - dxb1) + ((dyU.y - byU.y) - (dyC.y - byC.y)));

        *(float2*)(base + ij) = make_float2(fmaf(alpha, c0, se0),
                                            fmaf(alpha, c1, se1));
    } else {
#pragma unroll
        for (int t = 0; t < 2; ++t) {
            const int jj = j + t;
            const int idx = i * WW + jj;
            const int jm = (jj - 1) & MW, im = (i - 1) & MW;
            float dxb_c = __ldg(&dX[idx]) - __ldg(&bX[idx]);
            float dxb_l = __ldg(&dX[i * WW + jm]) - __ldg(&bX[i * WW + jm]);
            float dyb_c = __ldg(&dY[idx]) - __ldg(&bY[idx]);
            float dyb_u = __ldg(&dY[im * WW + jj]) - __ldg(&bY[im * WW + jj]);
            float se = sigma * ((dxb_l - dxb_c) + (dyb_u - dyb_c));
            float conv = 0.f;
#pragma unroll
            for (int p = 0; p < 3; ++p) {
                const int r = (i + p - 1) & MW;
#pragma unroll
                for (int q = 0; q < 3; ++q) {
                    const int c = (jj + q - 1) & MW;
                    conv = fmaf(__ldg(&STg[r * WW + c]),
                                __ldg(&w9[(2 - p) * 3 + (2 - q)]), conv);
                }
            }
            base[idx] = fmaf(alpha, conv, se);
        }
    }
}

// ---------------------------------------------------------------------------
// One fused _compute iteration: unconditional compute, gated stores.
// ---------------------------------------------------------------------------
template <int K>
__device__ __forceinline__ void iter_step(
    const float* __restrict__ in, float* __restrict__ out,
    float* __restrict__ CO, float* __restrict__ FA,
    const int* sio, const int* sco, const int* sabm, float* fa,
    float w0, float w1, float w2, float w3, float w4,
    float w5, float w6, float w7, float w8,
    float alpha, float bs, float g)
{
    // Phase A: first conv at decimated corners (no predicates)
#pragma unroll
    for (int s = 0; s < NSLOT; ++s) {
        const float* p = in + sio[s];
        const float2 r0 = lds2(p + 1);
        const float  a0 = p[0];
        const float2 r1 = lds2(p + BP + 1);
        const float  a1 = p[BP];
        const float2 r2 = lds2(p + 2 * BP + 1);
        const float  a2 = p[2 * BP];
        float acc = fmaf(a0, w0, r0.x * w1);
        acc = fmaf(r0.y, w2, acc);
        acc = fmaf(a1, w3, acc);
        acc = fmaf(r1.x, w4, acc);
        acc = fmaf(r1.y, w5, acc);
        acc = fmaf(a2, w6, acc);
        acc = fmaf(r2.x, w7, acc);
        acc = fmaf(r2.y, w8, acc);
        CO[sco[s]] = acc;
    }
    __syncthreads();

    // Phase B: second conv from corners + laplacian + f accumulation
#pragma unroll
    for (int s = 0; s < NSLOT; ++s) {
        const float* p = in + sio[s];
        const float2 t0 = lds2(p + 1);
        const float  l10 = p[BP];
        const float2 m1 = lds2(p + BP + 1);
        const float  l13 = p[BP + 3];
        const float  l20 = p[2 * BP];
        const float2 m2 = lds2(p + 2 * BP + 1);
        const float  l23 = p[2 * BP + 3];
        const float2 t3 = lds2(p + 3 * BP + 1);

        const float lap00 = 4.f * m1.x - l10 - m1.y - t0.x - m2.x;
        const float lap01 = 4.f * m1.y - m1.x - l13 - t0.y - m2.y;
        const float lap10 = 4.f * m2.x - l20 - m2.y - m1.x - t3.x;
        const float lap11 = 4.f * m2.y - m2.x - l23 - m1.y - t3.y;

        const float* co = CO + sco[s];
        const float o00 = co[0], o01 = co[1];
        const float o10 = co[COP], o11 = co[COP + 1];

        const float r00 = fmaf(alpha, o00 * w4, bs * lap00);
        const float r01 = fmaf(alpha, fmaf(o00, w5, o01 * w3), bs * lap01);
        const float r10 = fmaf(alpha, fmaf(o00, w7, o10 * w1), bs * lap10);
        const float r11 = fmaf(alpha,
            fmaf(o00, w8, fmaf(o01, w6, fmaf(o10, w2, o11 * w0))),
            bs * lap11);

        if (K < 5) {
            const int n = (sabm[s] >> 18) & 63;
            float* ob = out + sio[s] + BP + 1;
            if (n >= K) {                       // full interior quad (common)
                sts2(ob, r00, r01);
                sts2(ob + BP, r10, r11);
            } else {
                const int m = (sabm[s] >> 12) & 63;
                if (m >= K) {                   // partial edge quad (rare)
                    const int a = sabm[s] & 63, b = (sabm[s] >> 6) & 63;
                    const bool ch = (b <= 41 - K), rh = (a <= 41 - K);
                    ob[0] = r00;
                    if (ch) ob[1] = r01;
                    if (rh) { ob[BP] = r10; if (ch) ob[BP + 1] = r11; }
                }
            }
            // f accumulation: unpredicated (garbage gated at final store)
            fa[4 * s + 0] = fmaf(g, r00, fa[4 * s + 0]);
            fa[4 * s + 1] = fmaf(g, r01, fa[4 * s + 1]);
            fa[4 * s + 2] = fmaf(g, r10, fa[4 * s + 2]);
            fa[4 * s + 3] = fmaf(g, r11, fa[4 * s + 3]);
        } else {
            // K == 5: fold last term and store f to smem, gated by fm
            const int fm = (sabm[s] >> 24) & 15;
            if (fm) {
                const int a = sabm[s] & 63, b = (sabm[s] >> 6) & 63;
                float* fp = FA + (2 * a - 10) * FAP + (2 * b - 10);
                const float v00 = fmaf(g, r00, fa[4 * s + 0]);
                const float v01 = fmaf(g, r01, fa[4 * s + 1]);
                const float v10 = fmaf(g, r10, fa[4 * s + 2]);
                const float v11 = fmaf(g, r11, fa[4 * s + 3]);
                const bool r0ok = fm & 1, r1ok = fm & 2;
                const bool c0ok = fm & 4, c1ok = fm & 8;
                if (r0ok) {
                    if (c0ok && c1ok) sts2(fp, v00, v01);
                    else { if (c0ok) fp[0] = v00; if (c1ok) fp[1] = v01; }
                }
                if (r1ok) {
                    if (c0ok && c1ok) sts2(fp + FAP, v10, v11);
                    else { if (c0ok) fp[FAP] = v10; if (c1ok) fp[FAP + 1] = v11; }
                }
            }
        }
    }
    __syncthreads();
}

// ---------------------------------------------------------------------------
// Mega kernel
// ---------------------------------------------------------------------------
__global__ __launch_bounds__(NT, 2) void mega_kernel(
    const float* __restrict__ base0, const float* __restrict__ bX,
    const float* __restrict__ bY, const float* __restrict__ alpha_p,
    const float* __restrict__ beta0_p, const float* __restrict__ beta1_p,
    const float* __restrict__ sigma_p, const float* __restrict__ gamma,
    const float* __restrict__ w9, float* __restrict__ out)
{
    extern __shared__ __align__(16) float sm[];
    float* A  = sm;                 // 85*88
    float* B  = A + ASIZE;          // 85*88
    float* CO = B + ASIZE;          // 42*42 + pad
    float* FA = B;                  // aliases B (dead after iter 4)

    const int tid = threadIdx.x;
    const int gx0 = blockIdx.x * CORE;
    const int gy0 = blockIdx.y * CORE;

    const float w0 = __ldg(&w9[0]), w1 = __ldg(&w9[1]), w2 = __ldg(&w9[2]);
    const float w3 = __ldg(&w9[3]), w4 = __ldg(&w9[4]), w5 = __ldg(&w9[5]);
    const float w6 = __ldg(&w9[6]), w7 = __ldg(&w9[7]), w8 = __ldg(&w9[8]);
    const float alpha = __ldg(alpha_p);
    const float bs = __ldg(beta0_p) + __ldg(sigma_p);

    // --- fixed slot precompute --------------------------------------------
    int sio[NSLOT], sco[NSLOT], sabm[NSLOT];
#pragma unroll
    for (int s = 0; s < NSLOT; ++s) {
        const int q = tid + s * NT;
        if (q < NQ * NQ) {
            const int a = q / NQ + 1;
            const int b = q - (a - 1) * NQ + 1;
            sio[s] = (2 * a - 1) * BP + (2 * b - 1);
            sco[s] = (a - 1) * COP + (b - 1);
            int m = min(min(a, b), min(42 - a, 42 - b));
            int n = min(min(a, b), min(41 - a, 41 - b));
            int fm = ((a >= 5 && a <= 37) ? 1 : 0) |
                     ((a >= 5 && a <= 36) ? 2 : 0) |
                     ((b >= 5 && b <= 37) ? 4 : 0) |
                     ((b >= 5 && b <= 36) ? 8 : 0);
            sabm[s] = a | (b << 6) | (m << 12) | (n << 18) | (fm << 24);
        } else {
            // idle slot: alias slot (1,1) -> same alignment parity as real
            // slots (odd sio), results routed to CO dump cell, never stored
            // (m=n=0 < K, fm=0).
            sio[s] = SIO_IDLE; sco[s] = CO_DUMP; sabm[s] = 0;
        }
    }

    // --- load 85x85 base0 patch ------------------------------------------
    const bool interior = (blockIdx.x >= 1) & (blockIdx.x <= gridDim.x - 2) &
                          (blockIdx.y >= 1) & (blockIdx.y <= gridDim.y - 2);
    if (interior) {
        const float* src = base0 + (gy0 - 10) * WW + (gx0 - 10);
        for (int idx = tid; idx < B0 * 43; idx += NT) {
            const int r = idx / 43;
            const int c2 = idx - r * 43;
            const float2 v = __ldg((const float2*)(src + r * WW + 2 * c2));
            *(float2*)(A + r * BP + 2 * c2) = v;
        }
    } else {
        for (int idx = tid; idx < B0 * B0; idx += NT) {
            const int r = idx / B0;
            const int c = idx - r * B0;
            A[r * BP + c] = __ldg(&base0[((gy0 - 10 + r) & MW) * WW +
                                         ((gx0 - 10 + c) & MW)]);
        }
    }
    __syncthreads();

    // --- f-reg init: fa = gamma[0] * base0 (quad values) -------------------
    float fa[4 * NSLOT];
    const float g0 = __ldg(&gamma[0]);
#pragma unroll
    for (int s = 0; s < NSLOT; ++s) {
        const float* p = A + sio[s] + BP + 1;   // pixel (2a, 2b)
        const float2 u = lds2(p);
        const float2 v = lds2(p + BP);
        fa[4 * s + 0] = g0 * u.x;
        fa[4 * s + 1] = g0 * u.y;
        fa[4 * s + 2] = g0 * v.x;
        fa[4 * s + 3] = g0 * v.y;
    }

    iter_step<1>(A, B, CO, FA, sio, sco, sabm, fa,
                 w0, w1, w2, w3, w4, w5, w6, w7, w8, alpha, bs, __ldg(&gamma[1]));
    iter_step<2>(B, A, CO, FA, sio, sco, sabm, fa,
                 w0, w1, w2, w3, w4, w5, w6, w7, w8, alpha, bs, __ldg(&gamma[2]));
    iter_step<3>(A, B, CO, FA, sio, sco, sabm, fa,
                 w0, w1, w2, w3, w4, w5, w6, w7, w8, alpha, bs, __ldg(&gamma[3]));
    iter_step<4>(B, A, CO, FA, sio, sco, sabm, fa,
                 w0, w1, w2, w3, w4, w5, w6, w7, w8, alpha, bs, __ldg(&gamma[4]));
    // iter 5 reads A; writes f directly into FA (=B, dead since iter-4 sync)
    iter_step<5>(A, B, CO, FA, sio, sco, sabm, fa,
                 w0, w1, w2, w3, w4, w5, w6, w7, w8, alpha, bs, __ldg(&gamma[5]));

    // --- shrink / Bregman epilogue: 2 pixels per step ----------------------
    const float thr = __fdividef(__ldg(beta1_p), __ldg(sigma_p));
    for (int idx = tid; idx < 64 * 32; idx += NT) {
        const int r = idx >> 5;
        const int cp = idx & 31;
        const float* fr0 = FA + r * FAP + 2 * cp;
        const float2 f0 = lds2(fr0);
        const float fR = fr0[2];
        const float2 f1 = lds2(fr0 + FAP);
        const float dxf0 = f0.y - f0.x, dxf1 = fR - f0.y;
        const float dyf0 = f1.x - f0.x, dyf1 = f1.y - f0.y;
        const int ij = (gy0 + r) * WW + gx0 + 2 * cp;
        const float2 bx = __ldg((const float2*)(bX + ij));
        const float2 by = __ldg((const float2*)(bY + ij));
        const float px0 = dxf0 + bx.x, py0 = dyf0 + by.x;
        const float px1 = dxf1 + bx.y, py1 = dyf1 + by.y;
        const float n0 = sqrtf(fmaf(px0, px0, py0 * py0));
        const float n1 = sqrtf(fmaf(px1, px1, py1 * py1));
        const float sh0 = __fdividef(fmaxf(n0 - thr, 0.f), n0 + 1e-8f);
        const float sh1 = __fdividef(fmaxf(n1 - thr, 0.f), n1 + 1e-8f);
        const float dxn0 = px0 * sh0, dyn0 = py0 * sh0;
        const float dxn1 = px1 * sh1, dyn1 = py1 * sh1;
        *(float2*)(out + ij) = f0;
        *(float2*)(out + NPIX + ij) = make_float2(dxn0, dxn1);
        *(float2*)(out + 2 * NPIX + ij) = make_float2(dyn0, dyn1);
        *(float2*)(out + 3 * NPIX + ij) =
            make_float2(bx.x + dxf0 - dxn0, bx.y + dxf1 - dxn1);
        *(float2*)(out + 4 * NPIX + ij) =
            make_float2(by.x + dyf0 - dyn0, by.y + dyf1 - dyn1);
    }
}

static const int SMEM_BYTES = (2 * ASIZE + CO_SIZE) * 4;

extern "C" void kernel_launch(void* const* d_in, const int* in_sizes, int n_in,
                              void* d_out, int out_size)
{
    const float* STg   = (const float*)d_in[0];
    const float* dX    = (const float*)d_in[1];
    const float* dY    = (const float*)d_in[2];
    const float* bX    = (const float*)d_in[3];
    const float* bY    = (const float*)d_in[4];
    const float* alpha = (const float*)d_in[7];
    const float* beta0 = (const float*)d_in[8];
    const float* beta1 = (const float*)d_in[9];
    const float* sigma = (const float*)d_in[10];
    const float* gamma = (const float*)d_in[11];
    const float* w9    = (const float*)d_in[12];

    float* out = (float*)d_out;

    float* pB0;
    cudaGetSymbolAddress((void**)&pB0, g_base0);

    dim3 b1(32, 8), g1(WW / 64, HH / 8);
    stage0_kernel<<<g1, b1>>>(STg, dX, dY, bX, bY, alpha, sigma, w9, pB0);

    cudaFuncSetAttribute(mega_kernel,
                         cudaFuncAttributeMaxDynamicSharedMemorySize,
                         SMEM_BYTES);
    dim3 g2(WW / CORE, HH / CORE);
    mega_kernel<<<g2, NT, SMEM_BYTES>>>(pB0, bX, bY, alpha, beta0, beta1,
                                        sigma, gamma, w9, out);
}